// round 6
// baseline (speedup 1.0000x reference)
#include <cuda_runtime.h>
#include <math.h>

#define NMAX 200000
#define DFEAT 256
#define MNB   64
#define KSEL  3
#define NODES_PER_WARP 8

// Scratch (allocation-free): per-node projections.
__device__ float g_s_self[NMAX];
__device__ float g_s_all[NMAX];

// ---------------------------------------------------------------------------
// Kernel 1: one warp handles 8 nodes in 2 batches of 4. All 4 rows of a batch
// loaded up-front (8 LDG.128/lane in flight), then ONE exchange-halving
// butterfly reduces all 8 sums (4 nodes x {sa,sb}) in ~9 shfls total.
// Value-index mapping: idx bit2<-lane bit4, bit1<-lane bit3, bit0<-lane bit2;
// after the final two plain levels, lanes (lane&3)==0 hold sum idx=(lane>>2).
// idx = 2*i+0 -> sa of node i, 2*i+1 -> sb of node i.
// ---------------------------------------------------------------------------
__global__ void __launch_bounds__(256) score_kernel(const float* __restrict__ x,
                                                    const float* __restrict__ W,
                                                    const float* __restrict__ bias,
                                                    int N) {
    int warp = (blockIdx.x * 256 + threadIdx.x) >> 5;
    int lane = threadIdx.x & 31;
    int node0 = warp * NODES_PER_WARP;
    if (node0 >= N) return;

    const float4* wa4 = (const float4*)(W);          // W[0:256]
    const float4* wb4 = (const float4*)(W + DFEAT);  // W[256:512]
    float4 a0 = __ldg(wa4 + lane), a1 = __ldg(wa4 + lane + 32);
    float4 b0 = __ldg(wb4 + lane), b1 = __ldg(wb4 + lane + 32);
    float bb = bias[0];

    bool hi4 = (lane & 16) != 0;
    bool hi3 = (lane & 8) != 0;
    bool hi2 = (lane & 4) != 0;

#pragma unroll
    for (int batch = 0; batch < NODES_PER_WARP; batch += 4) {
        int nb0 = node0 + batch;

        float4 xv0[4], xv1[4];
#pragma unroll
        for (int i = 0; i < 4; i++) {
            int n = nb0 + i;
            if (n < N) {
                const float4* xr = (const float4*)(x + (size_t)n * DFEAT);
                xv0[i] = __ldg(xr + lane);
                xv1[i] = __ldg(xr + lane + 32);
            } else {
                xv0[i] = make_float4(0.f, 0.f, 0.f, 0.f);
                xv1[i] = make_float4(0.f, 0.f, 0.f, 0.f);
            }
        }

        float v[8];
#pragma unroll
        for (int i = 0; i < 4; i++) {
            float4 c0 = xv0[i], c1 = xv1[i];
            float ta, tb;
            ta  = c0.x * a0.x;          ta = fmaf(c0.y, a0.y, ta);
            ta  = fmaf(c0.z, a0.z, ta); ta = fmaf(c0.w, a0.w, ta);
            ta  = fmaf(c1.x, a1.x, ta); ta = fmaf(c1.y, a1.y, ta);
            ta  = fmaf(c1.z, a1.z, ta); ta = fmaf(c1.w, a1.w, ta);
            tb  = c0.x * b0.x;          tb = fmaf(c0.y, b0.y, tb);
            tb  = fmaf(c0.z, b0.z, tb); tb = fmaf(c0.w, b0.w, tb);
            tb  = fmaf(c1.x, b1.x, tb); tb = fmaf(c1.y, b1.y, tb);
            tb  = fmaf(c1.z, b1.z, tb); tb = fmaf(c1.w, b1.w, tb);
            v[2 * i]     = ta;
            v[2 * i + 1] = tb;
        }

        // Level 1 (xor 16): keep 4 values, idx bit2 <- lane bit4.
#pragma unroll
        for (int j = 0; j < 4; j++) {
            float s = hi4 ? v[j] : v[j + 4];
            float r = __shfl_xor_sync(0xffffffffu, s, 16);
            float k = hi4 ? v[j + 4] : v[j];
            v[j] = k + r;
        }
        // Level 2 (xor 8): keep 2 values, idx bit1 <- lane bit3.
#pragma unroll
        for (int j = 0; j < 2; j++) {
            float s = hi3 ? v[j] : v[j + 2];
            float r = __shfl_xor_sync(0xffffffffu, s, 8);
            float k = hi3 ? v[j + 2] : v[j];
            v[j] = k + r;
        }
        // Level 3 (xor 4): keep 1 value, idx bit0 <- lane bit2.
        {
            float s = hi2 ? v[0] : v[1];
            float r = __shfl_xor_sync(0xffffffffu, s, 4);
            float k = hi2 ? v[1] : v[0];
            v[0] = k + r;
        }
        // Final plain levels over lane bits 1,0.
        v[0] += __shfl_xor_sync(0xffffffffu, v[0], 2);
        v[0] += __shfl_xor_sync(0xffffffffu, v[0], 1);

        if ((lane & 3) == 0) {
            int idx = lane >> 2;              // 0..7
            int n = nb0 + (idx >> 1);
            if (n < N) {
                if (idx & 1) g_s_all[n]  = v[0];
                else         g_s_self[n] = v[0] + bb;
            }
        }
    }
}

// Order-preserving float<->uint mapping (total order on floats).
__device__ __forceinline__ unsigned fkey(float f) {
    unsigned u = __float_as_uint(f);
    return (u & 0x80000000u) ? ~u : (u | 0x80000000u);
}
__device__ __forceinline__ float funkey(unsigned u) {
    unsigned b = (u & 0x80000000u) ? (u & 0x7fffffffu) : ~u;
    return __uint_as_float(b);
}

// ---------------------------------------------------------------------------
// Kernel 2: TWO nodes per warp (16-lane segments), 4 candidate slots/lane.
// Per-lane presort (5 keyed compare-swaps) then 3 rounds touching only the
// per-lane HEAD: REDUX.max + ballot + ffs; the winning lane stores the
// selected id DIRECTLY and pops its head. Values written by lanes 0..2 with
// __expf. Gathers stay predicated on cnt (halves L1 wavefronts); the
// neighbor int4 load is unconditional (no divergent region; DRAM has slack).
// ---------------------------------------------------------------------------
__global__ void __launch_bounds__(256) topk_kernel(const int* __restrict__ neighbors,
                                                   const int* __restrict__ counts,
                                                   float* __restrict__ out,
                                                   int N) {
    int warp = (blockIdx.x * 256 + threadIdx.x) >> 5;
    int lane = threadIdx.x & 31;
    int half = lane >> 4;                 // segment id within warp
    int sub  = lane & 15;                 // lane within segment
    int node = warp * 2 + half;
    if (node >= N) return;

    unsigned mask = half ? 0xFFFF0000u : 0x0000FFFFu;

    int cnt  = __ldg(counts + node);
    int base = sub * 4;

    const int4* nb = (const int4*)(neighbors + (size_t)node * MNB);
    int4 nbr = __ldg(nb + sub);            // indices always valid node ids

    // key 0 marks invalid; fkey(any float) > 0. Predicated-off gathers emit
    // no L1 wavefront (load-bearing for the memory floor). cnt >= K.
    unsigned k0 = (base + 0 < cnt) ? fkey(__ldg(g_s_all + nbr.x)) : 0u;
    unsigned k1 = (base + 1 < cnt) ? fkey(__ldg(g_s_all + nbr.y)) : 0u;
    unsigned k2 = (base + 2 < cnt) ? fkey(__ldg(g_s_all + nbr.z)) : 0u;
    unsigned k3 = (base + 3 < cnt) ? fkey(__ldg(g_s_all + nbr.w)) : 0u;
    int c0 = nbr.x, c1 = nbr.y, c2 = nbr.z, c3 = nbr.w;

    // Presort the 4 (key,cand) pairs descending by key.
#define CSWAP(ka, ca, kb, cb)                                        \
    { bool sw = (kb) > (ka);                                         \
      unsigned tk = sw ? (kb) : (ka); (kb) = sw ? (ka) : (kb); (ka) = tk; \
      int tc = sw ? (cb) : (ca); (cb) = sw ? (ca) : (cb); (ca) = tc; }
    CSWAP(k0, c0, k1, c1)
    CSWAP(k2, c2, k3, c3)
    CSWAP(k0, c0, k2, c2)
    CSWAP(k1, c1, k3, c3)
    CSWAP(k1, c1, k2, c2)
#undef CSWAP

    float* osel = out + (size_t)N * KSEL;
    size_t ob = (size_t)node * KSEL;

    unsigned w0, w1, w2;
#pragma unroll
    for (int t = 0; t < KSEL; t++) {
        unsigned m = __reduce_max_sync(mask, k0);
        unsigned bal = __ballot_sync(mask, k0 == m);   // non-mask bits are 0
        int wl = __ffs((int)bal) - 1;                  // absolute lane id

        if (t == 0) w0 = m; else if (t == 1) w1 = m; else w2 = m;

        if (lane == wl) {                              // winner: store id, pop
            osel[ob + t] = (float)c0;                  // exact: ids < 2^24
            k0 = k1; c0 = c1;
            k1 = k2; c1 = c2;
            k2 = k3; c2 = c3;
        }
    }

    if (sub < KSEL) {                                  // parallel value epilogue
        unsigned wk = (sub == 0) ? w0 : (sub == 1) ? w1 : w2;
        float v = g_s_self[node] + funkey(wk);
        v = fmaxf(v, 0.01f * v);                       // leaky_relu (jax default)
        out[ob + sub] = __expf(v);
    }
}

extern "C" void kernel_launch(void* const* d_in, const int* in_sizes, int n_in,
                              void* d_out, int out_size) {
    // metadata order: node_features, neighbors, neighbor_counts, W, b
    const float* x         = (const float*)d_in[0];
    const int*   neighbors = (const int*)d_in[1];
    const int*   counts    = (const int*)d_in[2];
    const float* W         = (const float*)d_in[3];
    const float* bias      = (const float*)d_in[4];

    int N = in_sizes[0] / DFEAT;
    if (N > NMAX) N = NMAX;

    int warps1  = (N + NODES_PER_WARP - 1) / NODES_PER_WARP;
    int blocks1 = (warps1 + 7) / 8;
    score_kernel<<<blocks1, 256>>>(x, W, bias, N);

    int warps2  = (N + 1) / 2;               // 2 nodes per warp
    int blocks2 = (warps2 + 7) / 8;
    topk_kernel<<<blocks2, 256>>>(neighbors, counts, (float*)d_out, N);
}